// round 13
// baseline (speedup 1.0000x reference)
#include <cuda_runtime.h>
#include <cuda_bf16.h>
#include <math.h>
#include <stdint.h>

#define SQ    2048
#define DIM   2048
#define HEADS 16
#define KV    4
#define GG    4
#define DH    128
#define NW    255
#define NKEYS 256
#define NF    128
#define NSEL  4
#define SBS   16
#define SWIN  64
#define SCALE 0.08838834764831845f

#define KSPLIT 8
#define MROWS (KV*NW)        // 1020

// ---------------- scratch ----------------
// A-side: bf16 [M][2K]: cols [0,K)=hi, [K,2K)=lo
// B-side: uint32 pair-packed [K][N]: rows [0,K/2)=hi, [K/2,K)=lo
__device__ float g_h[SQ*DIM];
__device__ __nv_bfloat16 g_h2[(long)SQ*2*DIM];
__device__ float g_qkv[SQ*3072];
__device__ float g_comb[SQ*128];
__device__ float g_wcombpad[2048*128];
__device__ float g_bcombpad[128];
__device__ float g_b1cat[2*2048];
__device__ uint32_t g_wcomb2[1024*128*2];
__device__ uint32_t g_wqkv2[(long)2*1024*3072];
__device__ uint32_t g_kvw12[(long)2*2*1024*2048];   // [2 batches][hi;lo]
__device__ uint32_t g_kvw22[2*2*1024*128];          // [2 batches][hi;lo]
__device__ uint32_t g_wout2[(long)2*1024*2048];
__device__ __nv_bfloat16 g_kvwf2[(long)2*MROWS*4096];  // [2 batches][M][hi|lo]
__device__ __nv_bfloat16 g_hid2[(long)2*MROWS*4096];
__device__ float g_part[2*KSPLIT*MROWS*DH];
__device__ uint32_t g_ckT2[KV*128*256];
__device__ uint32_t g_cv2[KV*256*128];
__device__ __nv_bfloat16 g_qflat2[(long)KV*GG*SQ*256];
__device__ float g_sims[(long)KV*GG*SQ*NKEYS];
__device__ __nv_bfloat16 g_attn2[(long)KV*GG*SQ*512];
__device__ float g_coutf[(long)KV*GG*SQ*DH];
__device__ float g_rq[SQ*HEADS*DH];
__device__ float g_rk[KV*SQ*DH];
__device__ int   g_sel[KV*SQ*NSEL];
__device__ __nv_bfloat16 g_att2[(long)SQ*2*DIM];

// ---------------- helpers ----------------
__device__ __forceinline__ uint32_t pack_bf16x2(float f0, float f1) {
    uint32_t r;
    asm("cvt.rn.bf16x2.f32 %0, %1, %2;" : "=r"(r) : "f"(f1), "f"(f0));
    return r;
}
__device__ __forceinline__ void split2(float f0, float f1, uint32_t& hi, uint32_t& lo) {
    hi = pack_bf16x2(f0, f1);
    float h0 = __uint_as_float((hi & 0xFFFFu) << 16);
    float h1 = __uint_as_float(hi & 0xFFFF0000u);
    lo = pack_bf16x2(f0 - h0, f1 - h1);
}
__device__ __forceinline__ void bsplit(float v, __nv_bfloat16& h, __nv_bfloat16& l) {
    h = __float2bfloat16_rn(v);
    l = __float2bfloat16_rn(v - __bfloat162float(h));
}
__device__ __forceinline__ void mma_bf16(float* d, const uint32_t* a, const uint32_t* b) {
    asm volatile(
        "mma.sync.aligned.m16n8k16.row.col.f32.bf16.bf16.f32 "
        "{%0,%1,%2,%3}, {%4,%5,%6,%7}, {%8,%9}, {%0,%1,%2,%3};"
        : "+f"(d[0]), "+f"(d[1]), "+f"(d[2]), "+f"(d[3])
        : "r"(a[0]), "r"(a[1]), "r"(a[2]), "r"(a[3]),
          "r"(b[0]), "r"(b[1]));
}

// ---------------- RMSNorm (fp32 h + [hi|lo] bf16 h2) ----------------
__global__ void rmsnorm_kernel(const float* __restrict__ x, const float* __restrict__ g) {
    int s = blockIdx.x;
    int t = threadIdx.x;
    __shared__ float red[256];
    float acc = 0.f;
    for (int i = t; i < DIM; i += 256) { float v = x[s*DIM + i]; acc += v*v; }
    red[t] = acc; __syncthreads();
    for (int st = 128; st > 0; st >>= 1) {
        if (t < st) red[t] += red[t + st];
        __syncthreads();
    }
    float r = rsqrtf(red[0] / (float)DIM + 1e-6f);
    for (int i = t; i < DIM; i += 256) {
        float v = x[s*DIM + i] * r * g[i];
        g_h[s*DIM + i] = v;
        __nv_bfloat16 hb, lb; bsplit(v, hb, lb);
        long base = (long)s*4096;
        g_h2[base + i] = hb;
        g_h2[base + 2048 + i] = lb;
    }
}

// ---------------- pad comb weight/bias + concat b1 ----------------
__global__ void pad_comb(const float* __restrict__ w, const float* __restrict__ b,
                         const float* __restrict__ kb1, const float* __restrict__ vb1) {
    int i = blockIdx.x*256 + threadIdx.x;
    if (i < 128) g_bcombpad[i] = (i < 48) ? b[i] : 0.f;
    if (i < 2048) g_b1cat[i] = kb1[i];
    else if (i < 4096) g_b1cat[i] = vb1[i - 2048];
    if (i < 2048*128) {
        int r = i >> 7, c = i & 127;
        g_wcombpad[i] = (c < 48) ? w[r*48 + c] : 0.f;
    }
}

// ---------------- weight split (vectorized: 4 cols/thread) ----------------
__global__ void splitB4(const float* __restrict__ src, uint32_t* __restrict__ dst,
                        int K, int N) {
    long i = (long)blockIdx.x*256 + threadIdx.x;
    int n4cnt = N >> 2;
    long tot4 = (long)(K >> 1) * n4cnt;
    if (i >= tot4) return;
    int p = (int)(i / n4cnt);
    int n0 = (int)(i - (long)p*n4cnt) * 4;
    float4 r0 = *reinterpret_cast<const float4*>(&src[(long)(2*p)*N + n0]);
    float4 r1 = *reinterpret_cast<const float4*>(&src[(long)(2*p+1)*N + n0]);
    uint32_t h[4], l[4];
    split2(r0.x, r1.x, h[0], l[0]);
    split2(r0.y, r1.y, h[1], l[1]);
    split2(r0.z, r1.z, h[2], l[2]);
    split2(r0.w, r1.w, h[3], l[3]);
    long tot = (long)(K >> 1) * N;
    *reinterpret_cast<uint4*>(&dst[(long)p*N + n0]) = make_uint4(h[0], h[1], h[2], h[3]);
    *reinterpret_cast<uint4*>(&dst[tot + (long)p*N + n0]) = make_uint4(l[0], l[1], l[2], l[3]);
}

// ---------------- split-bf16 GEMM (batched + split-K via zsplit) ----------------
// blockIdx.z: zb = z / zsplit (batch), ks = z % zsplit (k-slice).
// zsplit>1 -> raw partials to C[z*M*N]; else C offset by zb*bsC, bias by zb*N.
#define AH_W 20
#define B_W  136
#define AH_BYTES (128*AH_W*4)
#define BH_BYTES (16*B_W*4)
#define OFF_AL (AH_BYTES)
#define OFF_BH (2*AH_BYTES)
#define OFF_BL (2*AH_BYTES + BH_BYTES)
#define BUFSZ  (2*AH_BYTES + 2*BH_BYTES)
#define GSMEM  (2*BUFSZ)

__global__ void __launch_bounds__(256, 2) bf2gemm(
    const __nv_bfloat16* __restrict__ A, const uint32_t* __restrict__ B,
    const float* __restrict__ bias, void* __restrict__ Cv,
    int M, int N, int K, int epi, int kslice,
    long bsA, long bsB, long bsC, int zsplit)
{
    extern __shared__ __align__(16) uint32_t dsm[];
    uint32_t smem0 = (uint32_t)__cvta_generic_to_shared(dsm);

    int zb = blockIdx.z / zsplit;
    int ks = blockIdx.z - zb*zsplit;
    A += (long)zb * bsA;
    B += (long)zb * bsB;
    if (bias != nullptr) bias += (long)zb * N;

    int tid = threadIdx.x;
    int lane = tid & 31, w = tid >> 5;
    int warp_m = w & 3, warp_n = w >> 2;
    int gid = lane >> 2, t4 = lane & 3;
    int row0 = blockIdx.y * 128, col0 = blockIdx.x * 128;
    int kbeg = ks * kslice;
    int nk = kslice >> 5;
    int Khalf = K >> 1;

    float acc[2][8][4];
    #pragma unroll
    for (int mf = 0; mf < 2; mf++)
        #pragma unroll
        for (int nf = 0; nf < 8; nf++)
            #pragma unroll
            for (int u = 0; u < 4; u++) acc[mf][nf][u] = 0.f;

    auto stage = [&](int kt, int buf) {
        int k0 = kbeg + (kt << 5);
        uint32_t base = smem0 + buf*BUFSZ;
        #pragma unroll
        for (int u = 0; u < 2; u++) {
            int idx = tid + u*256;
            int r = idx >> 2, ch = idx & 3;
            int gr = row0 + r;
            int grc = (gr < M) ? gr : 0;
            int sz = (gr < M) ? 16 : 0;
            long offh = ((long)grc*(2*K) + k0) * 2 + ch*16;
            asm volatile("cp.async.cg.shared.global [%0], [%1], 16, %2;"
                :: "r"(base + r*80 + ch*16), "l"((const char*)A + offh), "r"(sz));
            long offl = ((long)grc*(2*K) + K + k0) * 2 + ch*16;
            asm volatile("cp.async.cg.shared.global [%0], [%1], 16, %2;"
                :: "r"(base + OFF_AL + r*80 + ch*16), "l"((const char*)A + offl), "r"(sz));
        }
        int kp0 = k0 >> 1;
        #pragma unroll
        for (int u = 0; u < 2; u++) {
            int idx = tid + u*256;
            int r = idx >> 5, ch = idx & 31;
            long offbh = ((long)(kp0 + r)*N + col0) * 4 + ch*16;
            asm volatile("cp.async.cg.shared.global [%0], [%1], 16;"
                :: "r"(base + OFF_BH + r*544 + ch*16), "l"((const char*)B + offbh));
            long offbl = ((long)(Khalf + kp0 + r)*N + col0) * 4 + ch*16;
            asm volatile("cp.async.cg.shared.global [%0], [%1], 16;"
                :: "r"(base + OFF_BL + r*544 + ch*16), "l"((const char*)B + offbl));
        }
        asm volatile("cp.async.commit_group;");
    };

    stage(0, 0);
    int arb = warp_m*32, cb = warp_n*64;

    for (int kt = 0; kt < nk; kt++) {
        bool nxt = (kt + 1) < nk;
        if (nxt) { stage(kt+1, (kt+1) & 1); asm volatile("cp.async.wait_group 1;"); }
        else     { asm volatile("cp.async.wait_group 0;"); }
        __syncthreads();
        const uint32_t* Ah = dsm + (kt & 1)*(BUFSZ/4);
        const uint32_t* Al = Ah + AH_BYTES/4;
        const uint32_t* Bh = Ah + OFF_BH/4;
        const uint32_t* Bl = Ah + OFF_BL/4;
        #pragma unroll
        for (int s = 0; s < 2; s++) {
            uint32_t ah[2][4], al[2][4];
            #pragma unroll
            for (int mf = 0; mf < 2; mf++) {
                int r = arb + mf*16 + gid;
                int o0 = r*AH_W + s*8 + t4;
                int o1 = (r+8)*AH_W + s*8 + t4;
                ah[mf][0] = Ah[o0];   al[mf][0] = Al[o0];
                ah[mf][1] = Ah[o1];   al[mf][1] = Al[o1];
                ah[mf][2] = Ah[o0+4]; al[mf][2] = Al[o0+4];
                ah[mf][3] = Ah[o1+4]; al[mf][3] = Al[o1+4];
            }
            uint32_t bh[8][2], bl[8][2];
            #pragma unroll
            for (int nf = 0; nf < 8; nf++) {
                int c = cb + nf*8 + gid;
                int r0 = (s*8 + t4)*B_W + c;
                int r1 = (s*8 + t4 + 4)*B_W + c;
                bh[nf][0] = Bh[r0]; bl[nf][0] = Bl[r0];
                bh[nf][1] = Bh[r1]; bl[nf][1] = Bl[r1];
            }
            #pragma unroll
            for (int mf = 0; mf < 2; mf++)
                #pragma unroll
                for (int nf = 0; nf < 8; nf++) {
                    mma_bf16(acc[mf][nf], al[mf], bh[nf]);
                    mma_bf16(acc[mf][nf], ah[mf], bl[nf]);
                    mma_bf16(acc[mf][nf], ah[mf], bh[nf]);
                }
        }
        __syncthreads();
    }

    bool partial = (zsplit > 1);
    if (epi == 4) {
        __nv_bfloat16* C2 = (__nv_bfloat16*)Cv + (long)zb * bsC;
        #pragma unroll
        for (int mf = 0; mf < 2; mf++) {
            #pragma unroll
            for (int nf = 0; nf < 8; nf++) {
                int r0 = row0 + arb + mf*16 + gid;
                int c0 = col0 + cb + nf*8 + 2*t4;
                float b0 = bias[c0], b1 = bias[c0+1];
                #pragma unroll
                for (int half = 0; half < 2; half++) {
                    int r = r0 + half*8;
                    if (r >= M) continue;
                    float v0 = fmaxf(acc[mf][nf][half*2]   + b0, 0.f);
                    float v1 = fmaxf(acc[mf][nf][half*2+1] + b1, 0.f);
                    __nv_bfloat16 h0,l0,h1,l1;
                    bsplit(v0,h0,l0); bsplit(v1,h1,l1);
                    long base = (long)r*2*N;
                    C2[base + c0]     = h0; C2[base + c0 + 1]     = h1;
                    C2[base + N + c0] = l0; C2[base + N + c0 + 1] = l1;
                }
            }
        }
        return;
    }
    float* C = (float*)Cv;
    if (partial) C += (long)blockIdx.z * M * N;
    else C += (long)zb * bsC;
    #pragma unroll
    for (int mf = 0; mf < 2; mf++) {
        #pragma unroll
        for (int nf = 0; nf < 8; nf++) {
            int r0 = row0 + arb + mf*16 + gid;
            int c0 = col0 + cb + nf*8 + 2*t4;
            float b0 = 0.f, b1 = 0.f;
            if (!partial && epi >= 1) { b0 = bias[c0]; b1 = bias[c0+1]; }
            if (r0 < M) {
                float v0 = acc[mf][nf][0] + b0;
                float v1 = acc[mf][nf][1] + b1;
                if (!partial) {
                    if (epi == 2) { v0 = fmaxf(v0, 0.f); v1 = fmaxf(v1, 0.f); }
                    else if (epi == 3) { v0 = 1.f/(1.f+expf(-v0)); v1 = 1.f/(1.f+expf(-v1)); }
                }
                C[(long)r0*N + c0]     = v0;
                C[(long)r0*N + c0 + 1] = v1;
            }
            int r1 = r0 + 8;
            if (r1 < M) {
                float v2 = acc[mf][nf][2] + b0;
                float v3 = acc[mf][nf][3] + b1;
                if (!partial) {
                    if (epi == 2) { v2 = fmaxf(v2, 0.f); v3 = fmaxf(v3, 0.f); }
                    else if (epi == 3) { v2 = 1.f/(1.f+expf(-v2)); v3 = 1.f/(1.f+expf(-v3)); }
                }
                C[(long)r1*N + c0]     = v2;
                C[(long)r1*N + c0 + 1] = v3;
            }
        }
    }
}

// ---------------- window gather + pos add -> [hi|lo] bf16 (both batches) -----
__global__ void build_win(const float* __restrict__ k_pos, const float* __restrict__ v_pos) {
    int w = blockIdx.x, kh = blockIdx.y;
    long row = kh * NW + w;
    for (int i = threadIdx.x; i < 2048; i += 256) {
        int c = i >> 7, d = i & 127;
        int s = w * 8 + c;
        float kv_ = g_qkv[s*3072 + 2048 + kh*DH + d] + k_pos[kh*2048 + i];
        float vv_ = g_qkv[s*3072 + 2560 + kh*DH + d] + v_pos[kh*2048 + i];
        __nv_bfloat16 hb, lb;
        long base = row*4096;
        bsplit(kv_, hb, lb);
        g_kvwf2[base + i] = hb; g_kvwf2[base + 2048 + i] = lb;
        bsplit(vv_, hb, lb);
        long vbase = (long)MROWS*4096 + base;
        g_kvwf2[vbase + i] = hb; g_kvwf2[vbase + 2048 + i] = lb;
    }
}

// ---------------- assemble ckT2 (fused split-K reduce + bias) ----------------
__global__ void assemble_ck(const float* __restrict__ mem_kv, const float* __restrict__ b2) {
    int j = blockIdx.x, kh = blockIdx.y;
    int p = threadIdx.x;   // 0..63 d-pairs
    float v0, v1;
    if (j == 0) { v0 = mem_kv[kh*DH + 2*p]; v1 = mem_kv[kh*DH + 2*p + 1]; }
    else {
        long off = (long)(kh*NW + j - 1)*DH;
        v0 = b2[2*p]; v1 = b2[2*p + 1];
        #pragma unroll
        for (int z = 0; z < KSPLIT; z++) {
            const float* pz = g_part + (long)z*MROWS*DH + off;
            v0 += pz[2*p]; v1 += pz[2*p + 1];
        }
    }
    uint32_t hi, lo; split2(v0, v1, hi, lo);
    uint32_t* b = g_ckT2 + kh*(128*256);
    b[p*256 + j] = hi;
    b[(64 + p)*256 + j] = lo;
}

// ---------------- assemble cv2 (fused split-K reduce + bias) ----------------
__global__ void assemble_cv(const float* __restrict__ mem_kv, const float* __restrict__ b2) {
    int kp = blockIdx.x, kh = blockIdx.y;
    int d = threadIdx.x;
    int j0 = 2*kp, j1 = 2*kp + 1;
    const float* pv = g_part + (long)KSPLIT*MROWS*DH;
    float v0, v1;
    if (j0 == 0) v0 = mem_kv[KV*DH + kh*DH + d];
    else {
        long off0 = (long)(kh*NW + j0 - 1)*DH + d;
        v0 = b2[d];
        #pragma unroll
        for (int z = 0; z < KSPLIT; z++) v0 += pv[(long)z*MROWS*DH + off0];
    }
    {
        long off1 = (long)(kh*NW + j1 - 1)*DH + d;
        v1 = b2[d];
        #pragma unroll
        for (int z = 0; z < KSPLIT; z++) v1 += pv[(long)z*MROWS*DH + off1];
    }
    uint32_t hi, lo; split2(v0, v1, hi, lo);
    uint32_t* b = g_cv2 + kh*(256*128);
    b[kp*128 + d] = hi;
    b[(128 + kp)*128 + d] = lo;
}

// ---------------- RoPE + qflat fused ----------------
__global__ void rope_qflat() {
    int s = blockIdx.x;
    const float L2I = 0.20762050593046f;
    for (int p = threadIdx.x; p < 20 * 64; p += 256) {
        int head = p >> 6;
        int i = p & 63;
        float invf = exp2f(-(float)i * L2I);
        float ang = (float)s * invf;
        float sn, cs;
        sincosf(ang, &sn, &cs);
        if (head < HEADS) {
            const float* src = &g_qkv[s*3072 + head*DH];
            float t1 = src[2*i], t2 = src[2*i + 1];
            float* dst = &g_rq[(s*HEADS + head)*DH];
            dst[2*i]     = t1*cs - t2*sn;
            dst[2*i + 1] = t1*sn + t2*cs;
            long R = ((long)((head>>2)*GG + (head&3))*SQ + s);
            __nv_bfloat16 h1,l1,h2,l2;
            bsplit(t1,h1,l1); bsplit(t2,h2,l2);
            g_qflat2[R*256 + 2*i]       = h1;
            g_qflat2[R*256 + 2*i + 1]   = h2;
            g_qflat2[R*256 + 128 + 2*i]     = l1;
            g_qflat2[R*256 + 128 + 2*i + 1] = l2;
        } else {
            int kh = head - HEADS;
            const float* src = &g_qkv[s*3072 + 2048 + kh*DH];
            float t1 = src[2*i], t2 = src[2*i + 1];
            float* dst = &g_rk[(kh*SQ + s)*DH];
            dst[2*i]     = t1*cs - t2*sn;
            dst[2*i + 1] = t1*sn + t2*cs;
        }
    }
}

// ---------------- masked softmax + [hi|lo] write ----------------
__global__ void softmax_rows() {
    int w = threadIdx.x >> 5, lane = threadIdx.x & 31;
    long R = (long)blockIdx.x * 8 + w;
    int s = (int)(R & (SQ - 1));
    float* row = g_sims + R * NKEYS;
    float v[8];
    float m = -INFINITY;
    #pragma unroll
    for (int k2 = 0; k2 < 8; k2++) {
        int j = k2*32 + lane;
        bool valid = (j == 0) || (s > (j - 1) * 8 + 15);
        v[k2] = valid ? row[j]*SCALE : -INFINITY;
        m = fmaxf(m, v[k2]);
    }
    #pragma unroll
    for (int o = 16; o > 0; o >>= 1) m = fmaxf(m, __shfl_xor_sync(~0u, m, o));
    float sum = 0.f;
    #pragma unroll
    for (int k2 = 0; k2 < 8; k2++) { v[k2] = expf(v[k2] - m); sum += v[k2]; }
    #pragma unroll
    for (int o = 16; o > 0; o >>= 1) sum += __shfl_xor_sync(~0u, sum, o);
    float inv = 1.f / sum;
    __nv_bfloat16* a2 = g_attn2 + R * 512;
    #pragma unroll
    for (int k2 = 0; k2 < 8; k2++) {
        int j = k2*32 + lane;
        float p = v[k2] * inv;
        row[j] = p;
        __nv_bfloat16 hb, lb; bsplit(p, hb, lb);
        a2[j] = hb; a2[256 + j] = lb;
    }
}

// ---------------- importance + top-k ----------------
__global__ void topk_kernel() {
    int s = blockIdx.x, kv = blockIdx.y;
    int f = threadIdx.x;
    __shared__ float impsh[NF];
    float a = 0.f;
    #pragma unroll
    for (int g = 0; g < GG; g++) {
        const float* row = g_sims + ((long)(kv*GG + g)*SQ + s) * NKEYS;
        a += row[1 + 2*f];
        if (2*f + 1 < NW) a += row[2 + 2*f];
    }
    impsh[f] = (f < (s >> 4)) ? a * 0.125f : -1.0f;
    __syncthreads();
    if (f == 0) {
        for (int it = 0; it < NSEL; it++) {
            float best = -1e30f; int bi = 0;
            for (int j = 0; j < NF; j++)
                if (impsh[j] > best) { best = impsh[j]; bi = j; }
            g_sel[(kv*SQ + s)*NSEL + it] = (best > 0.f) ? bi : -1;
            impsh[bi] = -1e30f;
        }
    }
}

// ---------------- selected + sliding attention (warp per head, fused epi) ----
__global__ void __launch_bounds__(128) sel_sw2b() {
    int q = blockIdx.x, kv = blockIdx.y;
    int t = threadIdx.x, lane = t & 31, g = t >> 5;
    __shared__ int   kp[80];
    __shared__ float fat[4][80];
    __shared__ float wat[4][72];

    if (t < 80) {
        int pos, valid;
        if (t < 64) {
            int blk = g_sel[(kv*SQ + q)*NSEL + (t >> 4)];
            pos = blk*SBS + (t & 15);
            valid = (blk >= 0) && (pos <= q);
        } else {
            pos = (q & ~(SBS-1)) + (t - 64);
            valid = (pos <= q);
        }
        kp[t] = valid ? pos : -1;
    }
    __syncthreads();

    float4 qv = *reinterpret_cast<const float4*>(&g_rq[((long)q*HEADS + kv*GG + g)*DH + lane*4]);
    int kbase = (q >= SWIN) ? (q - SWIN) : 0;
    int cnt = q - kbase + 1;

    #pragma unroll 1
    for (int b = 0; b < 10; b++) {
        float part[8];
        #pragma unroll
        for (int jj = 0; jj < 8; jj++) {
            int pos = kp[b*8 + jj];
            float p = 0.f;
            if (pos >= 0) {
                float4 kk = *reinterpret_cast<const float4*>(&g_rk[((long)kv*SQ + pos)*DH + lane*4]);
                p = qv.x*kk.x + qv.y*kk.y + qv.z*kk.z + qv.w*kk.w;
            }
            part[jj] = p;
        }
        #pragma unroll
        for (int o = 16; o > 0; o >>= 1)
            #pragma unroll
            for (int jj = 0; jj < 8; jj++) part[jj] += __shfl_xor_sync(~0u, part[jj], o);
        if (lane < 8) {
            int j = b*8 + lane;
            fat[g][j] = (kp[j] >= 0) ? part[lane]*SCALE : -INFINITY;
        }
    }
    #pragma unroll 1
    for (int b = 0; b < 9; b++) {
        float part[8];
        #pragma unroll
        for (int jj = 0; jj < 8; jj++) {
            int j = b*8 + jj;
            float p = 0.f;
            if (j < cnt) {
                float4 kk = *reinterpret_cast<const float4*>(&g_rk[((long)kv*SQ + kbase + j)*DH + lane*4]);
                p = qv.x*kk.x + qv.y*kk.y + qv.z*kk.z + qv.w*kk.w;
            }
            part[jj] = p;
        }
        #pragma unroll
        for (int o = 16; o > 0; o >>= 1)
            #pragma unroll
            for (int jj = 0; jj < 8; jj++) part[jj] += __shfl_xor_sync(~0u, part[jj], o);
        if (lane < 8) {
            int j = b*8 + lane;
            wat[g][j] = (j < cnt) ? part[lane]*SCALE : -INFINITY;
        }
    }
    __syncwarp();

    {
        float v0 = fat[g][lane];
        float v1 = fat[g][lane + 32];
        float v2 = (lane < 16) ? fat[g][lane + 64] : -INFINITY;
        float m = fmaxf(v0, fmaxf(v1, v2));
        #pragma unroll
        for (int o = 16; o > 0; o >>= 1) m = fmaxf(m, __shfl_xor_sync(~0u, m, o));
        float e0 = expf(v0 - m), e1 = expf(v1 - m), e2 = (lane < 16) ? expf(v2 - m) : 0.f;
        float sum = e0 + e1 + e2;
        #pragma unroll
        for (int o = 16; o > 0; o >>= 1) sum += __shfl_xor_sync(~0u, sum, o);
        float inv = 1.f / sum;
        fat[g][lane] = e0 * inv;
        fat[g][lane + 32] = e1 * inv;
        if (lane < 16) fat[g][lane + 64] = e2 * inv;
    }
    {
        float v0 = wat[g][lane];
        float v1 = wat[g][lane + 32];
        float v2 = (lane < 8) ? wat[g][lane + 64] : -INFINITY;
        float m = fmaxf(v0, fmaxf(v1, v2));
        #pragma unroll
        for (int o = 16; o > 0; o >>= 1) m = fmaxf(m, __shfl_xor_sync(~0u, m, o));
        float e0 = expf(v0 - m), e1 = expf(v1 - m), e2 = (lane < 8) ? expf(v2 - m) : 0.f;
        float sum = e0 + e1 + e2;
        #pragma unroll
        for (int o = 16; o > 0; o >>= 1) sum += __shfl_xor_sync(~0u, sum, o);
        float inv = 1.f / sum;
        wat[g][lane] = e0 * inv;
        wat[g][lane + 32] = e1 * inv;
        if (lane < 8) wat[g][lane + 64] = e2 * inv;
    }
    __syncwarp();

    float4 fa = make_float4(0.f,0.f,0.f,0.f);
    float4 wa = make_float4(0.f,0.f,0.f,0.f);
    #pragma unroll 4
    for (int j = 0; j < 80; j++) {
        int pos = kp[j];
        if (pos >= 0) {
            float a = fat[g][j];
            float4 vv = *reinterpret_cast<const float4*>(&g_qkv[(long)pos*3072 + 2560 + kv*DH + lane*4]);
            fa.x += a*vv.x; fa.y += a*vv.y; fa.z += a*vv.z; fa.w += a*vv.w;
        }
    }
    #pragma unroll 4
    for (int j = 0; j < 65; j++) {
        if (j < cnt) {
            float a = wat[g][j];
            float4 vv = *reinterpret_cast<const float4*>(&g_qkv[(long)(kbase + j)*3072 + 2560 + kv*DH + lane*4]);
            wa.x += a*vv.x; wa.y += a*vv.y; wa.z += a*vv.z; wa.w += a*vv.w;
        }
    }

    int head = kv*GG + g;
    float g0 = g_comb[q*128 + head*3 + 0];
    float g1 = g_comb[q*128 + head*3 + 1];
    float g2 = g_comb[q*128 + head*3 + 2];
    float4 cv4 = *reinterpret_cast<const float4*>(&g_coutf[((long)(kv*GG + g)*SQ + q)*DH + lane*4]);
    float o0 = g0*cv4.x + g1*fa.x + g2*wa.x;
    float o1 = g0*cv4.y + g1*fa.y + g2*wa.y;
    float o2 = g0*cv4.z + g1*fa.z + g2*wa.z;
    float o3 = g0*cv4.w + g1*fa.w + g2*wa.w;
    uint32_t hi0, lo0, hi1, lo1;
    split2(o0, o1, hi0, lo0);
    split2(o2, o3, hi1, lo1);
    long idx = (long)q*4096 + head*128 + lane*4;
    *reinterpret_cast<uint2*>(&g_att2[idx])        = make_uint2(hi0, hi1);
    *reinterpret_cast<uint2*>(&g_att2[idx + 2048]) = make_uint2(lo0, lo1);
}

// ---------------- launcher ----------------
extern "C" void kernel_launch(void* const* d_in, const int* in_sizes, int n_in,
                              void* d_out, int out_size) {
    const float* x      = (const float*)d_in[0];
    const float* gnorm  = (const float*)d_in[1];
    const float* w_qkv  = (const float*)d_in[2];
    const float* k_pos  = (const float*)d_in[3];
    const float* v_pos  = (const float*)d_in[4];
    const float* mem_kv = (const float*)d_in[5];
    const float* kc_w1  = (const float*)d_in[6];
    const float* kc_b1  = (const float*)d_in[7];
    const float* kc_w2  = (const float*)d_in[8];
    const float* kc_b2  = (const float*)d_in[9];
    const float* vc_w1  = (const float*)d_in[10];
    const float* vc_b1  = (const float*)d_in[11];
    const float* vc_w2  = (const float*)d_in[12];
    const float* vc_b2  = (const float*)d_in[13];
    const float* w_comb = (const float*)d_in[14];
    const float* b_comb = (const float*)d_in[15];
    const float* w_out  = (const float*)d_in[16];
    float* out = (float*)d_out;

    float *h, *qkv, *comb, *part, *sims, *coutf, *wcombpad, *bcombpad, *b1cat;
    __nv_bfloat16 *h2, *kvwf2, *hid2, *qflat2, *attn2, *att2;
    uint32_t *wqkv2, *kvw12, *kvw22, *wout2, *wcomb2, *ckT2, *cv2;
    cudaGetSymbolAddress((void**)&h,       g_h);
    cudaGetSymbolAddress((void**)&h2,      g_h2);
    cudaGetSymbolAddress((void**)&qkv,     g_qkv);
    cudaGetSymbolAddress((void**)&comb,    g_comb);
    cudaGetSymbolAddress((void**)&wcombpad,g_wcombpad);
    cudaGetSymbolAddress((void**)&bcombpad,g_bcombpad);
    cudaGetSymbolAddress((void**)&b1cat,   g_b1cat);
    cudaGetSymbolAddress((void**)&wcomb2,  g_wcomb2);
    cudaGetSymbolAddress((void**)&part,    g_part);
    cudaGetSymbolAddress((void**)&sims,    g_sims);
    cudaGetSymbolAddress((void**)&coutf,   g_coutf);
    cudaGetSymbolAddress((void**)&kvwf2,   g_kvwf2);
    cudaGetSymbolAddress((void**)&hid2,    g_hid2);
    cudaGetSymbolAddress((void**)&qflat2,  g_qflat2);
    cudaGetSymbolAddress((void**)&attn2,   g_attn2);
    cudaGetSymbolAddress((void**)&att2,    g_att2);
    cudaGetSymbolAddress((void**)&wqkv2,   g_wqkv2);
    cudaGetSymbolAddress((void**)&kvw12,   g_kvw12);
    cudaGetSymbolAddress((void**)&kvw22,   g_kvw22);
    cudaGetSymbolAddress((void**)&wout2,   g_wout2);
    cudaGetSymbolAddress((void**)&ckT2,    g_ckT2);
    cudaGetSymbolAddress((void**)&cv2,     g_cv2);

    static bool attr_set = false;
    if (!attr_set) {
        cudaFuncSetAttribute(bf2gemm, cudaFuncAttributeMaxDynamicSharedMemorySize, GSMEM);
        attr_set = true;
    }

    const int MQ = GG*SQ;        // 8192
    const long W1B = (long)2*1024*2048;   // uint32 per layer-1 weight split
    const long W2B = (long)2*1024*128;    // uint32 per layer-2 weight split

    // weight splits ([hi;lo] pair-packed, vectorized)
    splitB4<<<(1024*768),  256>>>(w_qkv, wqkv2, 2048, 3072);       // 1024*3072/4/256 blocks
    splitB4<<<(1024*512),  256>>>(kc_w1, kvw12, 2048, 2048);
    splitB4<<<(1024*512),  256>>>(vc_w1, kvw12 + W1B, 2048, 2048);
    splitB4<<<128,         256>>>(kc_w2, kvw22, 2048, 128);
    splitB4<<<128,         256>>>(vc_w2, kvw22 + W2B, 2048, 128);
    splitB4<<<(1024*512),  256>>>(w_out, wout2, 2048, 2048);
    pad_comb<<<(2048*128)/256, 256>>>(w_comb, b_comb, kc_b1, vc_b1);
    splitB4<<<128, 256>>>(wcombpad, wcomb2, 2048, 128);

    rmsnorm_kernel<<<SQ, 256>>>(x, gnorm);

    // qkv = h @ w_qkv
    bf2gemm<<<dim3(3072/128, SQ/128), 256, GSMEM>>>(h2, wqkv2, nullptr, qkv,
        SQ, 3072, 2048, 0, 2048, 0, 0, 0, 1);
    // comb gates = sigmoid(h @ w_comb + b)  (padded N=128)
    bf2gemm<<<dim3(1, SQ/128), 256, GSMEM>>>(h2, wcomb2, bcombpad, comb,
        SQ, 128, 2048, 3, 2048, 0, 0, 0, 1);

    rope_qflat<<<SQ, 256>>>();
    build_win<<<dim3(NW, KV), 256>>>(k_pos, v_pos);

    // compression MLP layer-1: k & v batched (grid z = 2)
    bf2gemm<<<dim3(2048/128, 8, 2), 256, GSMEM>>>(kvwf2, kvw12, b1cat, hid2,
        MROWS, 2048, 2048, 4, 2048,
        (long)MROWS*4096, W1B, (long)MROWS*4096, 1);
    // layer-2: batched (2) x split-K (8) -> grid z = 16, raw partials
    bf2gemm<<<dim3(1, 8, 2*KSPLIT), 256, GSMEM>>>(hid2, kvw22, nullptr, part,
        MROWS, DH, 2048, 0, 2048/KSPLIT,
        (long)MROWS*4096, W2B, 0, KSPLIT);
    assemble_ck<<<dim3(NKEYS, KV), 64>>>(mem_kv, kc_b2);
    assemble_cv<<<dim3(128, KV), 128>>>(mem_kv, vc_b2);

    // compressed attention: sims = qflat2 @ ckT2 (batched over kv)
    bf2gemm<<<dim3(NKEYS/128, MQ/128, KV), 256, GSMEM>>>(qflat2, ckT2, nullptr, sims,
        MQ, NKEYS, 128, 0, 128, (long)MQ*256, (long)128*256, (long)MQ*NKEYS, 1);
    softmax_rows<<<KV*GG*SQ/8, 256>>>();
    topk_kernel<<<dim3(SQ, KV), 128>>>();
    // PV: cout = attn2 @ cv2
    bf2gemm<<<dim3(DH/128, MQ/128, KV), 256, GSMEM>>>(attn2, cv2, nullptr, coutf,
        MQ, DH, 256, 0, 256, (long)MQ*512, (long)256*128, (long)MQ*DH, 1);

    // fused selected + sliding + gate combine + att2 split
    sel_sw2b<<<dim3(SQ, KV), 128>>>();

    // out = att2 @ wout2
    bf2gemm<<<dim3(DIM/128, SQ/128), 256, GSMEM>>>(att2, wout2, nullptr, out,
        SQ, DIM, 2048, 0, 2048, 0, 0, 0, 1);
}

// round 14
// speedup vs baseline: 2.0462x; 2.0462x over previous
#include <cuda_runtime.h>
#include <cuda_bf16.h>
#include <math.h>
#include <stdint.h>

#define SQ    2048
#define DIM   2048
#define HEADS 16
#define KV    4
#define GG    4
#define DH    128
#define NW    255
#define NKEYS 256
#define NF    128
#define NSEL  4
#define SBS   16
#define SWIN  64
#define SCALE 0.08838834764831845f

#define KSPLIT 8
#define MROWS (KV*NW)        // 1020

// ---------------- scratch ----------------
// A-side: bf16 [M][2K]: cols [0,K)=hi, [K,2K)=lo
// B-side: uint32 pair-packed [K][N]: rows [0,K/2)=hi, [K/2,K)=lo
__device__ float g_h[SQ*DIM];
__device__ __nv_bfloat16 g_h2[(long)SQ*2*DIM];
__device__ float g_qkv[SQ*3072];
__device__ float g_comb[SQ*128];
__device__ float g_wcombpad[2048*128];
__device__ float g_bcombpad[128];
__device__ float g_b1cat[2*2048];
__device__ uint32_t g_wcomb2[1024*128*2];
__device__ uint32_t g_wqkv2[(long)2*1024*3072];
__device__ uint32_t g_kvw12[(long)2*2*1024*2048];   // [2 batches][hi;lo]
__device__ uint32_t g_kvw22[2*2*1024*128];          // [2 batches][hi;lo]
__device__ uint32_t g_wout2[(long)2*1024*2048];
__device__ __nv_bfloat16 g_kvwf2[(long)2*MROWS*4096];  // [2 batches][M][hi|lo]
__device__ __nv_bfloat16 g_hid2[(long)2*MROWS*4096];
__device__ float g_part[2*KSPLIT*MROWS*DH];
__device__ uint32_t g_ckT2[KV*128*256];
__device__ uint32_t g_cv2[KV*256*128];
__device__ __nv_bfloat16 g_qflat2[(long)KV*GG*SQ*256];
__device__ float g_sims[(long)KV*GG*SQ*NKEYS];
__device__ __nv_bfloat16 g_attn2[(long)KV*GG*SQ*512];
__device__ float g_coutf[(long)KV*GG*SQ*DH];
__device__ float g_rq[SQ*HEADS*DH];
__device__ float g_rk[KV*SQ*DH];
__device__ int   g_sel[KV*SQ*NSEL];
__device__ __nv_bfloat16 g_att2[(long)SQ*2*DIM];

// ---------------- helpers ----------------
__device__ __forceinline__ uint32_t pack_bf16x2(float f0, float f1) {
    uint32_t r;
    asm("cvt.rn.bf16x2.f32 %0, %1, %2;" : "=r"(r) : "f"(f1), "f"(f0));
    return r;
}
__device__ __forceinline__ void split2(float f0, float f1, uint32_t& hi, uint32_t& lo) {
    hi = pack_bf16x2(f0, f1);
    float h0 = __uint_as_float((hi & 0xFFFFu) << 16);
    float h1 = __uint_as_float(hi & 0xFFFF0000u);
    lo = pack_bf16x2(f0 - h0, f1 - h1);
}
__device__ __forceinline__ void bsplit(float v, __nv_bfloat16& h, __nv_bfloat16& l) {
    h = __float2bfloat16_rn(v);
    l = __float2bfloat16_rn(v - __bfloat162float(h));
}
__device__ __forceinline__ void mma_bf16(float* d, const uint32_t* a, const uint32_t* b) {
    asm volatile(
        "mma.sync.aligned.m16n8k16.row.col.f32.bf16.bf16.f32 "
        "{%0,%1,%2,%3}, {%4,%5,%6,%7}, {%8,%9}, {%0,%1,%2,%3};"
        : "+f"(d[0]), "+f"(d[1]), "+f"(d[2]), "+f"(d[3])
        : "r"(a[0]), "r"(a[1]), "r"(a[2]), "r"(a[3]),
          "r"(b[0]), "r"(b[1]));
}

// ---------------- RMSNorm (fp32 h + [hi|lo] bf16 h2) ----------------
__global__ void rmsnorm_kernel(const float* __restrict__ x, const float* __restrict__ g) {
    int s = blockIdx.x;
    int t = threadIdx.x;
    __shared__ float red[256];
    float acc = 0.f;
    for (int i = t; i < DIM; i += 256) { float v = x[s*DIM + i]; acc += v*v; }
    red[t] = acc; __syncthreads();
    for (int st = 128; st > 0; st >>= 1) {
        if (t < st) red[t] += red[t + st];
        __syncthreads();
    }
    float r = rsqrtf(red[0] / (float)DIM + 1e-6f);
    for (int i = t; i < DIM; i += 256) {
        float v = x[s*DIM + i] * r * g[i];
        g_h[s*DIM + i] = v;
        __nv_bfloat16 hb, lb; bsplit(v, hb, lb);
        long base = (long)s*4096;
        g_h2[base + i] = hb;
        g_h2[base + 2048 + i] = lb;
    }
}

// ---------------- pad comb weight/bias + concat b1 ----------------
__global__ void pad_comb(const float* __restrict__ w, const float* __restrict__ b,
                         const float* __restrict__ kb1, const float* __restrict__ vb1) {
    int i = blockIdx.x*256 + threadIdx.x;
    if (i < 128) g_bcombpad[i] = (i < 48) ? b[i] : 0.f;
    if (i < 2048) g_b1cat[i] = kb1[i];
    else if (i < 4096) g_b1cat[i] = vb1[i - 2048];
    if (i < 2048*128) {
        int r = i >> 7, c = i & 127;
        g_wcombpad[i] = (c < 48) ? w[r*48 + c] : 0.f;
    }
}

// ---------------- weight split (vectorized: 4 cols/thread) ----------------
__global__ void splitB4(const float* __restrict__ src, uint32_t* __restrict__ dst,
                        int K, int N) {
    long i = (long)blockIdx.x*256 + threadIdx.x;
    int n4cnt = N >> 2;
    long tot4 = (long)(K >> 1) * n4cnt;
    if (i >= tot4) return;
    int p = (int)(i / n4cnt);
    int n0 = (int)(i - (long)p*n4cnt) * 4;
    float4 r0 = *reinterpret_cast<const float4*>(&src[(long)(2*p)*N + n0]);
    float4 r1 = *reinterpret_cast<const float4*>(&src[(long)(2*p+1)*N + n0]);
    uint32_t h[4], l[4];
    split2(r0.x, r1.x, h[0], l[0]);
    split2(r0.y, r1.y, h[1], l[1]);
    split2(r0.z, r1.z, h[2], l[2]);
    split2(r0.w, r1.w, h[3], l[3]);
    long tot = (long)(K >> 1) * N;
    *reinterpret_cast<uint4*>(&dst[(long)p*N + n0]) = make_uint4(h[0], h[1], h[2], h[3]);
    *reinterpret_cast<uint4*>(&dst[tot + (long)p*N + n0]) = make_uint4(l[0], l[1], l[2], l[3]);
}

// ---------------- split-bf16 GEMM (batched + split-K via zsplit) ----------------
#define AH_W 20
#define B_W  136
#define AH_BYTES (128*AH_W*4)
#define BH_BYTES (16*B_W*4)
#define OFF_AL (AH_BYTES)
#define OFF_BH (2*AH_BYTES)
#define OFF_BL (2*AH_BYTES + BH_BYTES)
#define BUFSZ  (2*AH_BYTES + 2*BH_BYTES)
#define GSMEM  (2*BUFSZ)

__global__ void __launch_bounds__(256, 2) bf2gemm(
    const __nv_bfloat16* __restrict__ A, const uint32_t* __restrict__ B,
    const float* __restrict__ bias, void* __restrict__ Cv,
    int M, int N, int K, int epi, int kslice,
    long bsA, long bsB, long bsC, int zsplit)
{
    extern __shared__ __align__(16) uint32_t dsm[];
    uint32_t smem0 = (uint32_t)__cvta_generic_to_shared(dsm);

    int zb = blockIdx.z / zsplit;
    int ks = blockIdx.z - zb*zsplit;
    A += (long)zb * bsA;
    B += (long)zb * bsB;
    if (bias != nullptr) bias += (long)zb * N;

    int tid = threadIdx.x;
    int lane = tid & 31, w = tid >> 5;
    int warp_m = w & 3, warp_n = w >> 2;
    int gid = lane >> 2, t4 = lane & 3;
    int row0 = blockIdx.y * 128, col0 = blockIdx.x * 128;
    int kbeg = ks * kslice;
    int nk = kslice >> 5;
    int Khalf = K >> 1;

    float acc[2][8][4];
    #pragma unroll
    for (int mf = 0; mf < 2; mf++)
        #pragma unroll
        for (int nf = 0; nf < 8; nf++)
            #pragma unroll
            for (int u = 0; u < 4; u++) acc[mf][nf][u] = 0.f;

    auto stage = [&](int kt, int buf) {
        int k0 = kbeg + (kt << 5);
        uint32_t base = smem0 + buf*BUFSZ;
        #pragma unroll
        for (int u = 0; u < 2; u++) {
            int idx = tid + u*256;
            int r = idx >> 2, ch = idx & 3;
            int gr = row0 + r;
            int grc = (gr < M) ? gr : 0;
            int sz = (gr < M) ? 16 : 0;
            long offh = ((long)grc*(2*K) + k0) * 2 + ch*16;
            asm volatile("cp.async.cg.shared.global [%0], [%1], 16, %2;"
                :: "r"(base + r*80 + ch*16), "l"((const char*)A + offh), "r"(sz));
            long offl = ((long)grc*(2*K) + K + k0) * 2 + ch*16;
            asm volatile("cp.async.cg.shared.global [%0], [%1], 16, %2;"
                :: "r"(base + OFF_AL + r*80 + ch*16), "l"((const char*)A + offl), "r"(sz));
        }
        int kp0 = k0 >> 1;
        #pragma unroll
        for (int u = 0; u < 2; u++) {
            int idx = tid + u*256;
            int r = idx >> 5, ch = idx & 31;
            long offbh = ((long)(kp0 + r)*N + col0) * 4 + ch*16;
            asm volatile("cp.async.cg.shared.global [%0], [%1], 16;"
                :: "r"(base + OFF_BH + r*544 + ch*16), "l"((const char*)B + offbh));
            long offbl = ((long)(Khalf + kp0 + r)*N + col0) * 4 + ch*16;
            asm volatile("cp.async.cg.shared.global [%0], [%1], 16;"
                :: "r"(base + OFF_BL + r*544 + ch*16), "l"((const char*)B + offbl));
        }
        asm volatile("cp.async.commit_group;");
    };

    stage(0, 0);
    int arb = warp_m*32, cb = warp_n*64;

    for (int kt = 0; kt < nk; kt++) {
        bool nxt = (kt + 1) < nk;
        if (nxt) { stage(kt+1, (kt+1) & 1); asm volatile("cp.async.wait_group 1;"); }
        else     { asm volatile("cp.async.wait_group 0;"); }
        __syncthreads();
        const uint32_t* Ah = dsm + (kt & 1)*(BUFSZ/4);
        const uint32_t* Al = Ah + AH_BYTES/4;
        const uint32_t* Bh = Ah + OFF_BH/4;
        const uint32_t* Bl = Ah + OFF_BL/4;
        #pragma unroll
        for (int s = 0; s < 2; s++) {
            uint32_t ah[2][4], al[2][4];
            #pragma unroll
            for (int mf = 0; mf < 2; mf++) {
                int r = arb + mf*16 + gid;
                int o0 = r*AH_W + s*8 + t4;
                int o1 = (r+8)*AH_W + s*8 + t4;
                ah[mf][0] = Ah[o0];   al[mf][0] = Al[o0];
                ah[mf][1] = Ah[o1];   al[mf][1] = Al[o1];
                ah[mf][2] = Ah[o0+4]; al[mf][2] = Al[o0+4];
                ah[mf][3] = Ah[o1+4]; al[mf][3] = Al[o1+4];
            }
            uint32_t bh[8][2], bl[8][2];
            #pragma unroll
            for (int nf = 0; nf < 8; nf++) {
                int c = cb + nf*8 + gid;
                int r0 = (s*8 + t4)*B_W + c;
                int r1 = (s*8 + t4 + 4)*B_W + c;
                bh[nf][0] = Bh[r0]; bl[nf][0] = Bl[r0];
                bh[nf][1] = Bh[r1]; bl[nf][1] = Bl[r1];
            }
            #pragma unroll
            for (int mf = 0; mf < 2; mf++)
                #pragma unroll
                for (int nf = 0; nf < 8; nf++) {
                    mma_bf16(acc[mf][nf], al[mf], bh[nf]);
                    mma_bf16(acc[mf][nf], ah[mf], bl[nf]);
                    mma_bf16(acc[mf][nf], ah[mf], bh[nf]);
                }
        }
        __syncthreads();
    }

    bool partial = (zsplit > 1);
    if (epi == 4) {
        __nv_bfloat16* C2 = (__nv_bfloat16*)Cv + (long)zb * bsC;
        #pragma unroll
        for (int mf = 0; mf < 2; mf++) {
            #pragma unroll
            for (int nf = 0; nf < 8; nf++) {
                int r0 = row0 + arb + mf*16 + gid;
                int c0 = col0 + cb + nf*8 + 2*t4;
                float b0 = bias[c0], b1 = bias[c0+1];
                #pragma unroll
                for (int half = 0; half < 2; half++) {
                    int r = r0 + half*8;
                    if (r >= M) continue;
                    float v0 = fmaxf(acc[mf][nf][half*2]   + b0, 0.f);
                    float v1 = fmaxf(acc[mf][nf][half*2+1] + b1, 0.f);
                    __nv_bfloat16 h0,l0,h1,l1;
                    bsplit(v0,h0,l0); bsplit(v1,h1,l1);
                    long base = (long)r*2*N;
                    C2[base + c0]     = h0; C2[base + c0 + 1]     = h1;
                    C2[base + N + c0] = l0; C2[base + N + c0 + 1] = l1;
                }
            }
        }
        return;
    }
    float* C = (float*)Cv;
    if (partial) C += (long)blockIdx.z * M * N;
    else C += (long)zb * bsC;
    #pragma unroll
    for (int mf = 0; mf < 2; mf++) {
        #pragma unroll
        for (int nf = 0; nf < 8; nf++) {
            int r0 = row0 + arb + mf*16 + gid;
            int c0 = col0 + cb + nf*8 + 2*t4;
            float b0 = 0.f, b1 = 0.f;
            if (!partial && epi >= 1) { b0 = bias[c0]; b1 = bias[c0+1]; }
            if (r0 < M) {
                float v0 = acc[mf][nf][0] + b0;
                float v1 = acc[mf][nf][1] + b1;
                if (!partial) {
                    if (epi == 2) { v0 = fmaxf(v0, 0.f); v1 = fmaxf(v1, 0.f); }
                    else if (epi == 3) { v0 = 1.f/(1.f+expf(-v0)); v1 = 1.f/(1.f+expf(-v1)); }
                }
                C[(long)r0*N + c0]     = v0;
                C[(long)r0*N + c0 + 1] = v1;
            }
            int r1 = r0 + 8;
            if (r1 < M) {
                float v2 = acc[mf][nf][2] + b0;
                float v3 = acc[mf][nf][3] + b1;
                if (!partial) {
                    if (epi == 2) { v2 = fmaxf(v2, 0.f); v3 = fmaxf(v3, 0.f); }
                    else if (epi == 3) { v2 = 1.f/(1.f+expf(-v2)); v3 = 1.f/(1.f+expf(-v3)); }
                }
                C[(long)r1*N + c0]     = v2;
                C[(long)r1*N + c0 + 1] = v3;
            }
        }
    }
}

// ---------------- window gather + pos add -> [hi|lo] bf16 (both batches) -----
__global__ void build_win(const float* __restrict__ k_pos, const float* __restrict__ v_pos) {
    int w = blockIdx.x, kh = blockIdx.y;
    long row = kh * NW + w;
    for (int i = threadIdx.x; i < 2048; i += 256) {
        int c = i >> 7, d = i & 127;
        int s = w * 8 + c;
        float kv_ = g_qkv[s*3072 + 2048 + kh*DH + d] + k_pos[kh*2048 + i];
        float vv_ = g_qkv[s*3072 + 2560 + kh*DH + d] + v_pos[kh*2048 + i];
        __nv_bfloat16 hb, lb;
        long base = row*4096;
        bsplit(kv_, hb, lb);
        g_kvwf2[base + i] = hb; g_kvwf2[base + 2048 + i] = lb;
        bsplit(vv_, hb, lb);
        long vbase = (long)MROWS*4096 + base;
        g_kvwf2[vbase + i] = hb; g_kvwf2[vbase + 2048 + i] = lb;
    }
}

// ---------------- assemble ckT2 (fused split-K reduce + bias) ----------------
__global__ void assemble_ck(const float* __restrict__ mem_kv, const float* __restrict__ b2) {
    int j = blockIdx.x, kh = blockIdx.y;
    int p = threadIdx.x;   // 0..63 d-pairs
    float v0, v1;
    if (j == 0) { v0 = mem_kv[kh*DH + 2*p]; v1 = mem_kv[kh*DH + 2*p + 1]; }
    else {
        long off = (long)(kh*NW + j - 1)*DH;
        v0 = b2[2*p]; v1 = b2[2*p + 1];
        #pragma unroll
        for (int z = 0; z < KSPLIT; z++) {
            const float* pz = g_part + (long)z*MROWS*DH + off;
            v0 += pz[2*p]; v1 += pz[2*p + 1];
        }
    }
    uint32_t hi, lo; split2(v0, v1, hi, lo);
    uint32_t* b = g_ckT2 + kh*(128*256);
    b[p*256 + j] = hi;
    b[(64 + p)*256 + j] = lo;
}

// ---------------- assemble cv2 (fused split-K reduce + bias) ----------------
__global__ void assemble_cv(const float* __restrict__ mem_kv, const float* __restrict__ b2) {
    int kp = blockIdx.x, kh = blockIdx.y;
    int d = threadIdx.x;
    int j0 = 2*kp, j1 = 2*kp + 1;
    const float* pv = g_part + (long)KSPLIT*MROWS*DH;
    float v0, v1;
    if (j0 == 0) v0 = mem_kv[KV*DH + kh*DH + d];
    else {
        long off0 = (long)(kh*NW + j0 - 1)*DH + d;
        v0 = b2[d];
        #pragma unroll
        for (int z = 0; z < KSPLIT; z++) v0 += pv[(long)z*MROWS*DH + off0];
    }
    {
        long off1 = (long)(kh*NW + j1 - 1)*DH + d;
        v1 = b2[d];
        #pragma unroll
        for (int z = 0; z < KSPLIT; z++) v1 += pv[(long)z*MROWS*DH + off1];
    }
    uint32_t hi, lo; split2(v0, v1, hi, lo);
    uint32_t* b = g_cv2 + kh*(256*128);
    b[kp*128 + d] = hi;
    b[(128 + kp)*128 + d] = lo;
}

// ---------------- RoPE + qflat fused ----------------
__global__ void rope_qflat() {
    int s = blockIdx.x;
    const float L2I = 0.20762050593046f;
    for (int p = threadIdx.x; p < 20 * 64; p += 256) {
        int head = p >> 6;
        int i = p & 63;
        float invf = exp2f(-(float)i * L2I);
        float ang = (float)s * invf;
        float sn, cs;
        sincosf(ang, &sn, &cs);
        if (head < HEADS) {
            const float* src = &g_qkv[s*3072 + head*DH];
            float t1 = src[2*i], t2 = src[2*i + 1];
            float* dst = &g_rq[(s*HEADS + head)*DH];
            dst[2*i]     = t1*cs - t2*sn;
            dst[2*i + 1] = t1*sn + t2*cs;
            long R = ((long)((head>>2)*GG + (head&3))*SQ + s);
            __nv_bfloat16 h1,l1,h2,l2;
            bsplit(t1,h1,l1); bsplit(t2,h2,l2);
            g_qflat2[R*256 + 2*i]       = h1;
            g_qflat2[R*256 + 2*i + 1]   = h2;
            g_qflat2[R*256 + 128 + 2*i]     = l1;
            g_qflat2[R*256 + 128 + 2*i + 1] = l2;
        } else {
            int kh = head - HEADS;
            const float* src = &g_qkv[s*3072 + 2048 + kh*DH];
            float t1 = src[2*i], t2 = src[2*i + 1];
            float* dst = &g_rk[(kh*SQ + s)*DH];
            dst[2*i]     = t1*cs - t2*sn;
            dst[2*i + 1] = t1*sn + t2*cs;
        }
    }
}

// ---------------- masked softmax + [hi|lo] write ----------------
__global__ void softmax_rows() {
    int w = threadIdx.x >> 5, lane = threadIdx.x & 31;
    long R = (long)blockIdx.x * 8 + w;
    int s = (int)(R & (SQ - 1));
    float* row = g_sims + R * NKEYS;
    float v[8];
    float m = -INFINITY;
    #pragma unroll
    for (int k2 = 0; k2 < 8; k2++) {
        int j = k2*32 + lane;
        bool valid = (j == 0) || (s > (j - 1) * 8 + 15);
        v[k2] = valid ? row[j]*SCALE : -INFINITY;
        m = fmaxf(m, v[k2]);
    }
    #pragma unroll
    for (int o = 16; o > 0; o >>= 1) m = fmaxf(m, __shfl_xor_sync(~0u, m, o));
    float sum = 0.f;
    #pragma unroll
    for (int k2 = 0; k2 < 8; k2++) { v[k2] = expf(v[k2] - m); sum += v[k2]; }
    #pragma unroll
    for (int o = 16; o > 0; o >>= 1) sum += __shfl_xor_sync(~0u, sum, o);
    float inv = 1.f / sum;
    __nv_bfloat16* a2 = g_attn2 + R * 512;
    #pragma unroll
    for (int k2 = 0; k2 < 8; k2++) {
        int j = k2*32 + lane;
        float p = v[k2] * inv;
        row[j] = p;
        __nv_bfloat16 hb, lb; bsplit(p, hb, lb);
        a2[j] = hb; a2[256 + j] = lb;
    }
}

// ---------------- importance + top-k ----------------
__global__ void topk_kernel() {
    int s = blockIdx.x, kv = blockIdx.y;
    int f = threadIdx.x;
    __shared__ float impsh[NF];
    float a = 0.f;
    #pragma unroll
    for (int g = 0; g < GG; g++) {
        const float* row = g_sims + ((long)(kv*GG + g)*SQ + s) * NKEYS;
        a += row[1 + 2*f];
        if (2*f + 1 < NW) a += row[2 + 2*f];
    }
    impsh[f] = (f < (s >> 4)) ? a * 0.125f : -1.0f;
    __syncthreads();
    if (f == 0) {
        for (int it = 0; it < NSEL; it++) {
            float best = -1e30f; int bi = 0;
            for (int j = 0; j < NF; j++)
                if (impsh[j] > best) { best = impsh[j]; bi = j; }
            g_sel[(kv*SQ + s)*NSEL + it] = (best > 0.f) ? bi : -1;
            impsh[bi] = -1e30f;
        }
    }
}

// ---------------- selected + sliding attention (warp per head, fused epi) ----
__global__ void __launch_bounds__(128) sel_sw2b() {
    int q = blockIdx.x, kv = blockIdx.y;
    int t = threadIdx.x, lane = t & 31, g = t >> 5;
    __shared__ int   kp[80];
    __shared__ float fat[4][80];
    __shared__ float wat[4][72];

    if (t < 80) {
        int pos, valid;
        if (t < 64) {
            int blk = g_sel[(kv*SQ + q)*NSEL + (t >> 4)];
            pos = blk*SBS + (t & 15);
            valid = (blk >= 0) && (pos <= q);
        } else {
            pos = (q & ~(SBS-1)) + (t - 64);
            valid = (pos <= q);
        }
        kp[t] = valid ? pos : -1;
    }
    __syncthreads();

    float4 qv = *reinterpret_cast<const float4*>(&g_rq[((long)q*HEADS + kv*GG + g)*DH + lane*4]);
    int kbase = (q >= SWIN) ? (q - SWIN) : 0;
    int cnt = q - kbase + 1;

    #pragma unroll 1
    for (int b = 0; b < 10; b++) {
        float part[8];
        #pragma unroll
        for (int jj = 0; jj < 8; jj++) {
            int pos = kp[b*8 + jj];
            float p = 0.f;
            if (pos >= 0) {
                float4 kk = *reinterpret_cast<const float4*>(&g_rk[((long)kv*SQ + pos)*DH + lane*4]);
                p = qv.x*kk.x + qv.y*kk.y + qv.z*kk.z + qv.w*kk.w;
            }
            part[jj] = p;
        }
        #pragma unroll
        for (int o = 16; o > 0; o >>= 1)
            #pragma unroll
            for (int jj = 0; jj < 8; jj++) part[jj] += __shfl_xor_sync(~0u, part[jj], o);
        if (lane < 8) {
            int j = b*8 + lane;
            fat[g][j] = (kp[j] >= 0) ? part[lane]*SCALE : -INFINITY;
        }
    }
    #pragma unroll 1
    for (int b = 0; b < 9; b++) {
        float part[8];
        #pragma unroll
        for (int jj = 0; jj < 8; jj++) {
            int j = b*8 + jj;
            float p = 0.f;
            if (j < cnt) {
                float4 kk = *reinterpret_cast<const float4*>(&g_rk[((long)kv*SQ + kbase + j)*DH + lane*4]);
                p = qv.x*kk.x + qv.y*kk.y + qv.z*kk.z + qv.w*kk.w;
            }
            part[jj] = p;
        }
        #pragma unroll
        for (int o = 16; o > 0; o >>= 1)
            #pragma unroll
            for (int jj = 0; jj < 8; jj++) part[jj] += __shfl_xor_sync(~0u, part[jj], o);
        if (lane < 8) {
            int j = b*8 + lane;
            wat[g][j] = (j < cnt) ? part[lane]*SCALE : -INFINITY;
        }
    }
    __syncwarp();

    {
        float v0 = fat[g][lane];
        float v1 = fat[g][lane + 32];
        float v2 = (lane < 16) ? fat[g][lane + 64] : -INFINITY;
        float m = fmaxf(v0, fmaxf(v1, v2));
        #pragma unroll
        for (int o = 16; o > 0; o >>= 1) m = fmaxf(m, __shfl_xor_sync(~0u, m, o));
        float e0 = expf(v0 - m), e1 = expf(v1 - m), e2 = (lane < 16) ? expf(v2 - m) : 0.f;
        float sum = e0 + e1 + e2;
        #pragma unroll
        for (int o = 16; o > 0; o >>= 1) sum += __shfl_xor_sync(~0u, sum, o);
        float inv = 1.f / sum;
        fat[g][lane] = e0 * inv;
        fat[g][lane + 32] = e1 * inv;
        if (lane < 16) fat[g][lane + 64] = e2 * inv;
    }
    {
        float v0 = wat[g][lane];
        float v1 = wat[g][lane + 32];
        float v2 = (lane < 8) ? wat[g][lane + 64] : -INFINITY;
        float m = fmaxf(v0, fmaxf(v1, v2));
        #pragma unroll
        for (int o = 16; o > 0; o >>= 1) m = fmaxf(m, __shfl_xor_sync(~0u, m, o));
        float e0 = expf(v0 - m), e1 = expf(v1 - m), e2 = (lane < 8) ? expf(v2 - m) : 0.f;
        float sum = e0 + e1 + e2;
        #pragma unroll
        for (int o = 16; o > 0; o >>= 1) sum += __shfl_xor_sync(~0u, sum, o);
        float inv = 1.f / sum;
        wat[g][lane] = e0 * inv;
        wat[g][lane + 32] = e1 * inv;
        if (lane < 8) wat[g][lane + 64] = e2 * inv;
    }
    __syncwarp();

    float4 fa = make_float4(0.f,0.f,0.f,0.f);
    float4 wa = make_float4(0.f,0.f,0.f,0.f);
    #pragma unroll 4
    for (int j = 0; j < 80; j++) {
        int pos = kp[j];
        if (pos >= 0) {
            float a = fat[g][j];
            float4 vv = *reinterpret_cast<const float4*>(&g_qkv[(long)pos*3072 + 2560 + kv*DH + lane*4]);
            fa.x += a*vv.x; fa.y += a*vv.y; fa.z += a*vv.z; fa.w += a*vv.w;
        }
    }
    #pragma unroll 4
    for (int j = 0; j < 65; j++) {
        if (j < cnt) {
            float a = wat[g][j];
            float4 vv = *reinterpret_cast<const float4*>(&g_qkv[(long)(kbase + j)*3072 + 2560 + kv*DH + lane*4]);
            wa.x += a*vv.x; wa.y += a*vv.y; wa.z += a*vv.z; wa.w += a*vv.w;
        }
    }

    int head = kv*GG + g;
    float g0 = g_comb[q*128 + head*3 + 0];
    float g1 = g_comb[q*128 + head*3 + 1];
    float g2 = g_comb[q*128 + head*3 + 2];
    float4 cv4 = *reinterpret_cast<const float4*>(&g_coutf[((long)(kv*GG + g)*SQ + q)*DH + lane*4]);
    float o0 = g0*cv4.x + g1*fa.x + g2*wa.x;
    float o1 = g0*cv4.y + g1*fa.y + g2*wa.y;
    float o2 = g0*cv4.z + g1*fa.z + g2*wa.z;
    float o3 = g0*cv4.w + g1*fa.w + g2*wa.w;
    uint32_t hi0, lo0, hi1, lo1;
    split2(o0, o1, hi0, lo0);
    split2(o2, o3, hi1, lo1);
    long idx = (long)q*4096 + head*128 + lane*4;
    *reinterpret_cast<uint2*>(&g_att2[idx])        = make_uint2(hi0, hi1);
    *reinterpret_cast<uint2*>(&g_att2[idx + 2048]) = make_uint2(lo0, lo1);
}

// ---------------- launcher ----------------
extern "C" void kernel_launch(void* const* d_in, const int* in_sizes, int n_in,
                              void* d_out, int out_size) {
    const float* x      = (const float*)d_in[0];
    const float* gnorm  = (const float*)d_in[1];
    const float* w_qkv  = (const float*)d_in[2];
    const float* k_pos  = (const float*)d_in[3];
    const float* v_pos  = (const float*)d_in[4];
    const float* mem_kv = (const float*)d_in[5];
    const float* kc_w1  = (const float*)d_in[6];
    const float* kc_b1  = (const float*)d_in[7];
    const float* kc_w2  = (const float*)d_in[8];
    const float* kc_b2  = (const float*)d_in[9];
    const float* vc_w1  = (const float*)d_in[10];
    const float* vc_b1  = (const float*)d_in[11];
    const float* vc_w2  = (const float*)d_in[12];
    const float* vc_b2  = (const float*)d_in[13];
    const float* w_comb = (const float*)d_in[14];
    const float* b_comb = (const float*)d_in[15];
    const float* w_out  = (const float*)d_in[16];
    float* out = (float*)d_out;

    float *h, *qkv, *comb, *part, *sims, *coutf, *wcombpad, *bcombpad, *b1cat;
    __nv_bfloat16 *h2, *kvwf2, *hid2, *qflat2, *attn2, *att2;
    uint32_t *wqkv2, *kvw12, *kvw22, *wout2, *wcomb2, *ckT2, *cv2;
    cudaGetSymbolAddress((void**)&h,       g_h);
    cudaGetSymbolAddress((void**)&h2,      g_h2);
    cudaGetSymbolAddress((void**)&qkv,     g_qkv);
    cudaGetSymbolAddress((void**)&comb,    g_comb);
    cudaGetSymbolAddress((void**)&wcombpad,g_wcombpad);
    cudaGetSymbolAddress((void**)&bcombpad,g_bcombpad);
    cudaGetSymbolAddress((void**)&b1cat,   g_b1cat);
    cudaGetSymbolAddress((void**)&wcomb2,  g_wcomb2);
    cudaGetSymbolAddress((void**)&part,    g_part);
    cudaGetSymbolAddress((void**)&sims,    g_sims);
    cudaGetSymbolAddress((void**)&coutf,   g_coutf);
    cudaGetSymbolAddress((void**)&kvwf2,   g_kvwf2);
    cudaGetSymbolAddress((void**)&hid2,    g_hid2);
    cudaGetSymbolAddress((void**)&qflat2,  g_qflat2);
    cudaGetSymbolAddress((void**)&attn2,   g_attn2);
    cudaGetSymbolAddress((void**)&att2,    g_att2);
    cudaGetSymbolAddress((void**)&wqkv2,   g_wqkv2);
    cudaGetSymbolAddress((void**)&kvw12,   g_kvw12);
    cudaGetSymbolAddress((void**)&kvw22,   g_kvw22);
    cudaGetSymbolAddress((void**)&wout2,   g_wout2);
    cudaGetSymbolAddress((void**)&ckT2,    g_ckT2);
    cudaGetSymbolAddress((void**)&cv2,     g_cv2);

    static bool attr_set = false;
    if (!attr_set) {
        cudaFuncSetAttribute(bf2gemm, cudaFuncAttributeMaxDynamicSharedMemorySize, GSMEM);
        attr_set = true;
    }

    const int MQ = GG*SQ;        // 8192
    const long W1B = (long)2*1024*2048;   // uint32 per layer-1 weight split
    const long W2B = (long)2*1024*128;    // uint32 per layer-2 weight split

    // weight splits ([hi;lo] pair-packed, vectorized) — grids = tot4/256
    splitB4<<<(1024*3072/4 + 255)/256, 256>>>(w_qkv, wqkv2, 2048, 3072);
    splitB4<<<(1024*2048/4 + 255)/256, 256>>>(kc_w1, kvw12, 2048, 2048);
    splitB4<<<(1024*2048/4 + 255)/256, 256>>>(vc_w1, kvw12 + W1B, 2048, 2048);
    splitB4<<<(1024*128/4  + 255)/256, 256>>>(kc_w2, kvw22, 2048, 128);
    splitB4<<<(1024*128/4  + 255)/256, 256>>>(vc_w2, kvw22 + W2B, 2048, 128);
    splitB4<<<(1024*2048/4 + 255)/256, 256>>>(w_out, wout2, 2048, 2048);
    pad_comb<<<(2048*128)/256, 256>>>(w_comb, b_comb, kc_b1, vc_b1);
    splitB4<<<(1024*128/4 + 255)/256, 256>>>(wcombpad, wcomb2, 2048, 128);

    rmsnorm_kernel<<<SQ, 256>>>(x, gnorm);

    // qkv = h @ w_qkv
    bf2gemm<<<dim3(3072/128, SQ/128), 256, GSMEM>>>(h2, wqkv2, nullptr, qkv,
        SQ, 3072, 2048, 0, 2048, 0, 0, 0, 1);
    // comb gates = sigmoid(h @ w_comb + b)  (padded N=128)
    bf2gemm<<<dim3(1, SQ/128), 256, GSMEM>>>(h2, wcomb2, bcombpad, comb,
        SQ, 128, 2048, 3, 2048, 0, 0, 0, 1);

    rope_qflat<<<SQ, 256>>>();
    build_win<<<dim3(NW, KV), 256>>>(k_pos, v_pos);

    // compression MLP layer-1: k & v batched (grid z = 2)
    bf2gemm<<<dim3(2048/128, 8, 2), 256, GSMEM>>>(kvwf2, kvw12, b1cat, hid2,
        MROWS, 2048, 2048, 4, 2048,
        (long)MROWS*4096, W1B, (long)MROWS*4096, 1);
    // layer-2: batched (2) x split-K (8) -> grid z = 16, raw partials
    bf2gemm<<<dim3(1, 8, 2*KSPLIT), 256, GSMEM>>>(hid2, kvw22, nullptr, part,
        MROWS, DH, 2048, 0, 2048/KSPLIT,
        (long)MROWS*4096, W2B, 0, KSPLIT);
    assemble_ck<<<dim3(NKEYS, KV), 64>>>(mem_kv, kc_b2);
    assemble_cv<<<dim3(128, KV), 128>>>(mem_kv, vc_b2);

    // compressed attention: sims = qflat2 @ ckT2 (batched over kv)
    bf2gemm<<<dim3(NKEYS/128, MQ/128, KV), 256, GSMEM>>>(qflat2, ckT2, nullptr, sims,
        MQ, NKEYS, 128, 0, 128, (long)MQ*256, (long)128*256, (long)MQ*NKEYS, 1);
    softmax_rows<<<KV*GG*SQ/8, 256>>>();
    topk_kernel<<<dim3(SQ, KV), 128>>>();
    // PV: cout = attn2 @ cv2
    bf2gemm<<<dim3(DH/128, MQ/128, KV), 256, GSMEM>>>(attn2, cv2, nullptr, coutf,
        MQ, DH, 256, 0, 256, (long)MQ*512, (long)256*128, (long)MQ*DH, 1);

    // fused selected + sliding + gate combine + att2 split
    sel_sw2b<<<dim3(SQ, KV), 128>>>();

    // out = att2 @ wout2
    bf2gemm<<<dim3(DIM/128, SQ/128), 256, GSMEM>>>(att2, wout2, nullptr, out,
        SQ, DIM, 2048, 0, 2048, 0, 0, 0, 1);
}